// round 2
// baseline (speedup 1.0000x reference)
#include <cuda_runtime.h>
#include <math.h>

#define EPS 1e-5f

// Problem dims (fixed by setup_inputs)
#define B_    2
#define C_    256
#define NPIX  4096   // 64*64
#define HEADS 8
#define HD    32
#define AREA  4
#define NA    1024   // NPIX/AREA

// Ps pitch (floats). 132 = 128+4 -> row-to-row bank offset of 4, breaking the
// 4-way LDS conflict of the PV phase while keeping 16B alignment (132 % 4 == 0).
#define PSP 132

// ---------------- scratch (device globals, no allocation) ----------------
__device__ float g_qk[(size_t)B_ * 512 * NPIX];   // qk conv+BN output (B,512,N)
__device__ float g_v [(size_t)B_ * C_  * NPIX];   // v conv+BN output  (B,256,N)
__device__ float g_pp[(size_t)B_ * C_  * NPIX];   // PE conv+BN output (B,256,N)
__device__ float g_o [(size_t)B_ * C_  * NPIX];   // attention output  (B,256,N)

// =====================================================================
// Kernel 1: fused qk (512 oc) + v (256 oc) 1x1 conv GEMM with folded BN.
// C = W(768x256) * X(256 x 8192), tiles 128oc x 128pix, 256 thr, 8x8 micro.
// =====================================================================
__global__ void __launch_bounds__(256) k_qkv(
    const float* __restrict__ x,
    const float* __restrict__ w_qk, const float* __restrict__ w_v,
    const float* __restrict__ qk_g, const float* __restrict__ qk_b,
    const float* __restrict__ qk_m, const float* __restrict__ qk_v,
    const float* __restrict__ v_g,  const float* __restrict__ v_b,
    const float* __restrict__ v_m,  const float* __restrict__ v_v)
{
    __shared__ float As[16 * 128];   // [c16][oc128]
    __shared__ float Bs[16 * 128];   // [c16][pix128]

    const int tid = threadIdx.x;
    const int p0  = blockIdx.x * 128;       // global pixel tile start
    const int b   = p0 >> 12;
    const int n0  = p0 & (NPIX - 1);
    const int oc0 = blockIdx.y * 128;
    const int ty  = tid >> 4, tx = tid & 15;

    float acc[8][8];
#pragma unroll
    for (int i = 0; i < 8; i++)
#pragma unroll
        for (int j = 0; j < 8; j++) acc[i][j] = 0.f;

    // A-tile loader mapping: 2 threads per oc row, 8 consecutive c each
    const int oc_l  = tid >> 1;
    const int cpart = (tid & 1) * 8;
    const int ocg   = oc0 + oc_l;
    const float* wrow = (ocg < 512) ? (w_qk + (size_t)ocg * 256)
                                    : (w_v  + (size_t)(ocg - 512) * 256);

    for (int c0 = 0; c0 < 256; c0 += 16) {
        float4 wa = *(const float4*)(wrow + c0 + cpart);
        float4 wb = *(const float4*)(wrow + c0 + cpart + 4);
        As[(cpart + 0) * 128 + oc_l] = wa.x;
        As[(cpart + 1) * 128 + oc_l] = wa.y;
        As[(cpart + 2) * 128 + oc_l] = wa.z;
        As[(cpart + 3) * 128 + oc_l] = wa.w;
        As[(cpart + 4) * 128 + oc_l] = wb.x;
        As[(cpart + 5) * 128 + oc_l] = wb.y;
        As[(cpart + 6) * 128 + oc_l] = wb.z;
        As[(cpart + 7) * 128 + oc_l] = wb.w;
#pragma unroll
        for (int it = 0; it < 2; it++) {
            int e4 = tid + it * 256;          // 0..511 float4s
            int c_l = e4 >> 5, p4 = e4 & 31;
            float4 xv = *(const float4*)(x + (((size_t)(b * 256 + c0 + c_l)) << 12)
                                           + n0 + p4 * 4);
            *(float4*)(Bs + c_l * 128 + p4 * 4) = xv;
        }
        __syncthreads();
#pragma unroll
        for (int kk = 0; kk < 16; kk++) {
            float4 a0 = *(float4*)(As + kk * 128 + ty * 8);
            float4 a1 = *(float4*)(As + kk * 128 + ty * 8 + 4);
            float4 b0 = *(float4*)(Bs + kk * 128 + tx * 8);
            float4 b1 = *(float4*)(Bs + kk * 128 + tx * 8 + 4);
            float av[8] = {a0.x, a0.y, a0.z, a0.w, a1.x, a1.y, a1.z, a1.w};
            float bv[8] = {b0.x, b0.y, b0.z, b0.w, b1.x, b1.y, b1.z, b1.w};
#pragma unroll
            for (int i = 0; i < 8; i++)
#pragma unroll
                for (int j = 0; j < 8; j++) acc[i][j] += av[i] * bv[j];
        }
        __syncthreads();
    }

#pragma unroll
    for (int i = 0; i < 8; i++) {
        int oc = oc0 + ty * 8 + i;
        float s, t;
        float* dst;
        if (oc < 512) {
            float sc = __ldg(qk_g + oc) * rsqrtf(__ldg(qk_v + oc) + EPS);
            s = sc; t = __ldg(qk_b + oc) - __ldg(qk_m + oc) * sc;
            dst = g_qk + (((size_t)(b * 512 + oc)) << 12) + n0;
        } else {
            int o2 = oc - 512;
            float sc = __ldg(v_g + o2) * rsqrtf(__ldg(v_v + o2) + EPS);
            s = sc; t = __ldg(v_b + o2) - __ldg(v_m + o2) * sc;
            dst = g_v + (((size_t)(b * 256 + o2)) << 12) + n0;
        }
        float4 r0 = make_float4(acc[i][0] * s + t, acc[i][1] * s + t,
                                acc[i][2] * s + t, acc[i][3] * s + t);
        float4 r1 = make_float4(acc[i][4] * s + t, acc[i][5] * s + t,
                                acc[i][6] * s + t, acc[i][7] * s + t);
        *(float4*)(dst + tx * 8)     = r0;
        *(float4*)(dst + tx * 8 + 4) = r1;
    }
}

// =====================================================================
// Kernel 2: depthwise 5x5 PE conv (cross-correlation, pad 2) + BN on g_v
// =====================================================================
__global__ void __launch_bounds__(256) k_pe(
    const float* __restrict__ w_pe,
    const float* __restrict__ pe_g, const float* __restrict__ pe_b,
    const float* __restrict__ pe_m, const float* __restrict__ pe_v)
{
    int id = blockIdx.x * 256 + threadIdx.x;     // < 2*256*4096
    int n  = id & 4095;
    int bc = id >> 12;
    int c  = bc & 255;
    int hh = n >> 6, w = n & 63;
    const float* vptr = g_v + ((size_t)bc << 12);
    const float* wp   = w_pe + c * 25;
    float acc = 0.f;
#pragma unroll
    for (int ky = 0; ky < 5; ky++) {
        int y = hh + ky - 2;
        if ((unsigned)y < 64u) {
#pragma unroll
            for (int kx = 0; kx < 5; kx++) {
                int xx = w + kx - 2;
                if ((unsigned)xx < 64u)
                    acc += vptr[y * 64 + xx] * __ldg(wp + ky * 5 + kx);
            }
        }
    }
    float sc = __ldg(pe_g + c) * rsqrtf(__ldg(pe_v + c) + EPS);
    g_pp[id] = acc * sc + (__ldg(pe_b + c) - __ldg(pe_m + c) * sc);
}

// =====================================================================
// Kernel 3: attention. Block = (n-tile of 128 rows) x (ba,head).
// Online softmax over 8 K/V chunks of 128. Na=1024, hd=32.
// smem: Qs[32][128], Ks[32][128], Vsm[128][33] (transposed), Ps[128][PSP],
//       sc_s[128], rs_s[128]
// =====================================================================
#define ATT_SMEM_FLOATS (32*128 + 32*128 + 128*33 + 128*PSP + 128 + 128)
#define ATT_SMEM_BYTES  (ATT_SMEM_FLOATS * 4)

__global__ void __launch_bounds__(256, 1) k_attn()
{
    extern __shared__ float sm[];
    float* Qs   = sm;                    // [d][n]   pitch 128
    float* Ks   = Qs + 32 * 128;         // [d][m]   pitch 128
    float* Vsm  = Ks + 32 * 128;         // [m][d]   pitch 33 (transposed)
    float* Ps   = Vsm + 128 * 33;        // [n][m]   pitch PSP (also reused as Os[d][n])
    float* sc_s = Ps + 128 * PSP;        // per-row chunk rescale
    float* rs_s = sc_s + 128;            // per-row softmax denom

    const int tid   = threadIdx.x;
    const int tileN = blockIdx.x;        // 0..7
    const int bah   = blockIdx.y;        // 0..63
    const int ba = bah >> 3, h = bah & 7;
    const int b  = ba >> 2,  a = ba & 3;
    const int n0 = tileN * 128;
    const float qscale = 0.17677669529663687f;   // 32^-0.5

    const size_t qbase = (((size_t)(b * 512 + h * 32)) << 12) + a * 1024 + n0;
    const size_t kbase = (((size_t)(b * 512 + 256 + h * 32)) << 12) + a * 1024;
    const size_t vbase = (((size_t)(b * 256 + h * 32)) << 12) + a * 1024;

    // load Q tile (scaled)
#pragma unroll
    for (int it = 0; it < 4; it++) {
        int e4 = tid + it * 256;              // 0..1023 float4s
        int d = e4 >> 5, c4 = e4 & 31;
        float4 qv = *(const float4*)(g_qk + qbase + (size_t)d * 4096 + c4 * 4);
        qv.x *= qscale; qv.y *= qscale; qv.z *= qscale; qv.w *= qscale;
        *(float4*)(Qs + d * 128 + c4 * 4) = qv;
    }

    const int ty  = tid >> 4, tx  = tid & 15;   // softmax ownership (8n x 8m micro)
    const int tyo = tid >> 3, txo = tid & 7;    // PV ownership (4n x 4d micro)

    float rm[8], rs[8];
#pragma unroll
    for (int i = 0; i < 8; i++) { rm[i] = -1e30f; rs[i] = 0.f; }
    float o[4][4];
#pragma unroll
    for (int i = 0; i < 4; i++)
#pragma unroll
        for (int j = 0; j < 4; j++) o[i][j] = 0.f;

    __syncthreads();

    for (int m0 = 0; m0 < NA; m0 += 128) {
        // ---- load K chunk (float4) and V chunk (transposed, scalar) ----
#pragma unroll
        for (int it = 0; it < 4; it++) {
            int e4 = tid + it * 256;
            int d = e4 >> 5, c4 = e4 & 31;
            float4 kv = *(const float4*)(g_qk + kbase + (size_t)d * 4096 + m0 + c4 * 4);
            *(float4*)(Ks + d * 128 + c4 * 4) = kv;
        }
#pragma unroll
        for (int it = 0; it < 16; it++) {
            int e = tid + it * 256;               // 0..4095
            int d = e >> 7, m = e & 127;
            Vsm[m * 33 + d] = g_v[vbase + (size_t)d * 4096 + m0 + m];
        }
        __syncthreads();

        // ---- S = (Q^T K) chunk, 8x8 micro ----
        float s[8][8];
#pragma unroll
        for (int i = 0; i < 8; i++)
#pragma unroll
            for (int j = 0; j < 8; j++) s[i][j] = 0.f;
#pragma unroll
        for (int d = 0; d < 32; d++) {
            float4 qa = *(float4*)(Qs + d * 128 + ty * 8);
            float4 qb = *(float4*)(Qs + d * 128 + ty * 8 + 4);
            float4 ka = *(float4*)(Ks + d * 128 + tx * 8);
            float4 kb = *(float4*)(Ks + d * 128 + tx * 8 + 4);
            float qv[8] = {qa.x, qa.y, qa.z, qa.w, qb.x, qb.y, qb.z, qb.w};
            float kv[8] = {ka.x, ka.y, ka.z, ka.w, kb.x, kb.y, kb.z, kb.w};
#pragma unroll
            for (int i = 0; i < 8; i++)
#pragma unroll
                for (int j = 0; j < 8; j++) s[i][j] += qv[i] * kv[j];
        }

        // ---- online softmax per row (half-warp = 16 threads share a row set) ----
#pragma unroll
        for (int i = 0; i < 8; i++) {
            float cm = s[i][0];
#pragma unroll
            for (int j = 1; j < 8; j++) cm = fmaxf(cm, s[i][j]);
            cm = fmaxf(cm, __shfl_xor_sync(0xffffffffu, cm, 1, 16));
            cm = fmaxf(cm, __shfl_xor_sync(0xffffffffu, cm, 2, 16));
            cm = fmaxf(cm, __shfl_xor_sync(0xffffffffu, cm, 4, 16));
            cm = fmaxf(cm, __shfl_xor_sync(0xffffffffu, cm, 8, 16));
            float newm = fmaxf(rm[i], cm);
            float sc   = __expf(rm[i] - newm);
            float p[8], psum = 0.f;
#pragma unroll
            for (int j = 0; j < 8; j++) { p[j] = __expf(s[i][j] - newm); psum += p[j]; }
            psum += __shfl_xor_sync(0xffffffffu, psum, 1, 16);
            psum += __shfl_xor_sync(0xffffffffu, psum, 2, 16);
            psum += __shfl_xor_sync(0xffffffffu, psum, 4, 16);
            psum += __shfl_xor_sync(0xffffffffu, psum, 8, 16);
            rs[i] = rs[i] * sc + psum;
            rm[i] = newm;
            int n = ty * 8 + i;
            if (tx == 0) sc_s[n] = sc;
            *(float4*)(Ps + n * PSP + tx * 8)     = make_float4(p[0], p[1], p[2], p[3]);
            *(float4*)(Ps + n * PSP + tx * 8 + 4) = make_float4(p[4], p[5], p[6], p[7]);
        }
        __syncthreads();

        // ---- O = O*sc + P @ V^T, 4n x 4d micro ----
        float scv[4];
#pragma unroll
        for (int i = 0; i < 4; i++) scv[i] = sc_s[tyo * 4 + i];
#pragma unroll
        for (int i = 0; i < 4; i++)
#pragma unroll
            for (int j = 0; j < 4; j++) o[i][j] *= scv[i];

#pragma unroll 4
        for (int m = 0; m < 128; m++) {
            float v0 = Vsm[m * 33 + txo * 4 + 0];
            float v1 = Vsm[m * 33 + txo * 4 + 1];
            float v2 = Vsm[m * 33 + txo * 4 + 2];
            float v3 = Vsm[m * 33 + txo * 4 + 3];
            float p0 = Ps[(tyo * 4 + 0) * PSP + m];
            float p1 = Ps[(tyo * 4 + 1) * PSP + m];
            float p2 = Ps[(tyo * 4 + 2) * PSP + m];
            float p3 = Ps[(tyo * 4 + 3) * PSP + m];
            o[0][0] += p0 * v0; o[0][1] += p0 * v1; o[0][2] += p0 * v2; o[0][3] += p0 * v3;
            o[1][0] += p1 * v0; o[1][1] += p1 * v1; o[1][2] += p1 * v2; o[1][3] += p1 * v3;
            o[2][0] += p2 * v0; o[2][1] += p2 * v1; o[2][2] += p2 * v2; o[2][3] += p2 * v3;
            o[3][0] += p3 * v0; o[3][1] += p3 * v1; o[3][2] += p3 * v2; o[3][3] += p3 * v3;
        }
        __syncthreads();
    }

    // ---- finalize: normalize, stage to smem [d][n], coalesced store ----
    if (tx == 0) {
#pragma unroll
        for (int i = 0; i < 8; i++) rs_s[ty * 8 + i] = rs[i];
    }
    __syncthreads();
#pragma unroll
    for (int i = 0; i < 4; i++) {
        float inv = 1.0f / rs_s[tyo * 4 + i];
#pragma unroll
        for (int j = 0; j < 4; j++)
            Ps[(txo * 4 + j) * PSP + tyo * 4 + i] = o[i][j] * inv;   // Os[d][n]
    }
    __syncthreads();
    const size_t obase = (((size_t)(b * 256 + h * 32)) << 12) + a * 1024 + n0;
#pragma unroll
    for (int it = 0; it < 4; it++) {
        int e4 = tid + it * 256;
        int d = e4 >> 5, c4 = e4 & 31;
        *(float4*)(g_o + obase + (size_t)d * 4096 + c4 * 4) =
            *(float4*)(Ps + d * PSP + c4 * 4);
    }
}

// =====================================================================
// Kernel 4: proj 1x1 conv GEMM with folded BN, input = g_o + g_pp.
// =====================================================================
__global__ void __launch_bounds__(256) k_proj(
    const float* __restrict__ w_proj,
    const float* __restrict__ pr_g, const float* __restrict__ pr_b,
    const float* __restrict__ pr_m, const float* __restrict__ pr_v,
    float* __restrict__ out)
{
    __shared__ float As[16 * 128];
    __shared__ float Bs[16 * 128];

    const int tid = threadIdx.x;
    const int p0  = blockIdx.x * 128;
    const int b   = p0 >> 12;
    const int n0  = p0 & (NPIX - 1);
    const int oc0 = blockIdx.y * 128;
    const int ty  = tid >> 4, tx = tid & 15;

    float acc[8][8];
#pragma unroll
    for (int i = 0; i < 8; i++)
#pragma unroll
        for (int j = 0; j < 8; j++) acc[i][j] = 0.f;

    const int oc_l  = tid >> 1;
    const int cpart = (tid & 1) * 8;
    const float* wrow = w_proj + (size_t)(oc0 + oc_l) * 256;

    for (int c0 = 0; c0 < 256; c0 += 16) {
        float4 wa = *(const float4*)(wrow + c0 + cpart);
        float4 wb = *(const float4*)(wrow + c0 + cpart + 4);
        As[(cpart + 0) * 128 + oc_l] = wa.x;
        As[(cpart + 1) * 128 + oc_l] = wa.y;
        As[(cpart + 2) * 128 + oc_l] = wa.z;
        As[(cpart + 3) * 128 + oc_l] = wa.w;
        As[(cpart + 4) * 128 + oc_l] = wb.x;
        As[(cpart + 5) * 128 + oc_l] = wb.y;
        As[(cpart + 6) * 128 + oc_l] = wb.z;
        As[(cpart + 7) * 128 + oc_l] = wb.w;
#pragma unroll
        for (int it = 0; it < 2; it++) {
            int e4 = tid + it * 256;
            int c_l = e4 >> 5, p4 = e4 & 31;
            size_t idx = (((size_t)(b * 256 + c0 + c_l)) << 12) + n0 + p4 * 4;
            float4 ov = *(const float4*)(g_o + idx);
            float4 pv = *(const float4*)(g_pp + idx);
            float4 xv = make_float4(ov.x + pv.x, ov.y + pv.y, ov.z + pv.z, ov.w + pv.w);
            *(float4*)(Bs + c_l * 128 + p4 * 4) = xv;
        }
        __syncthreads();
#pragma unroll
        for (int kk = 0; kk < 16; kk++) {
            float4 a0 = *(float4*)(As + kk * 128 + ty * 8);
            float4 a1 = *(float4*)(As + kk * 128 + ty * 8 + 4);
            float4 b0 = *(float4*)(Bs + kk * 128 + tx * 8);
            float4 b1 = *(float4*)(Bs + kk * 128 + tx * 8 + 4);
            float av[8] = {a0.x, a0.y, a0.z, a0.w, a1.x, a1.y, a1.z, a1.w};
            float bv[8] = {b0.x, b0.y, b0.z, b0.w, b1.x, b1.y, b1.z, b1.w};
#pragma unroll
            for (int i = 0; i < 8; i++)
#pragma unroll
                for (int j = 0; j < 8; j++) acc[i][j] += av[i] * bv[j];
        }
        __syncthreads();
    }

#pragma unroll
    for (int i = 0; i < 8; i++) {
        int oc = oc0 + ty * 8 + i;
        float sc = __ldg(pr_g + oc) * rsqrtf(__ldg(pr_v + oc) + EPS);
        float t  = __ldg(pr_b + oc) - __ldg(pr_m + oc) * sc;
        float* dst = out + (((size_t)(b * 256 + oc)) << 12) + n0;
        float4 r0 = make_float4(acc[i][0] * sc + t, acc[i][1] * sc + t,
                                acc[i][2] * sc + t, acc[i][3] * sc + t);
        float4 r1 = make_float4(acc[i][4] * sc + t, acc[i][5] * sc + t,
                                acc[i][6] * sc + t, acc[i][7] * sc + t);
        *(float4*)(dst + tx * 8)     = r0;
        *(float4*)(dst + tx * 8 + 4) = r1;
    }
}

// =====================================================================
// launch
// =====================================================================
extern "C" void kernel_launch(void* const* d_in, const int* in_sizes, int n_in,
                              void* d_out, int out_size)
{
    const float *x, *w_qk, *w_v, *w_pe, *w_proj;
    const float *qk_g, *qk_b, *qk_m, *qk_v;
    const float *v_g, *v_b, *v_m, *v_v;
    const float *pe_g, *pe_b, *pe_m, *pe_v;
    const float *pr_g, *pr_b, *pr_m, *pr_v;

    #define F(i) ((const float*)d_in[(i)])
    if (in_sizes[2] == 512) {
        // reference-signature order:
        // x, w_qk, qk_g,b,m,v, w_v, v_g,b,m,v, w_pe, pe_g,b,m,v, w_proj, pr_g,b,m,v
        x = F(0);  w_qk = F(1);
        qk_g = F(2);  qk_b = F(3);  qk_m = F(4);  qk_v = F(5);
        w_v = F(6);
        v_g = F(7);   v_b = F(8);   v_m = F(9);   v_v = F(10);
        w_pe = F(11);
        pe_g = F(12); pe_b = F(13); pe_m = F(14); pe_v = F(15);
        w_proj = F(16);
        pr_g = F(17); pr_b = F(18); pr_m = F(19); pr_v = F(20);
    } else {
        // dict-insertion order:
        // x, w_qk, w_v, w_pe, w_proj, qk_g,b,m,v, v_g,b,m,v, pe_g,b,m,v, pr_g,b,m,v
        x = F(0); w_qk = F(1); w_v = F(2); w_pe = F(3); w_proj = F(4);
        qk_g = F(5);  qk_b = F(6);  qk_m = F(7);  qk_v = F(8);
        v_g = F(9);   v_b = F(10);  v_m = F(11);  v_v = F(12);
        pe_g = F(13); pe_b = F(14); pe_m = F(15); pe_v = F(16);
        pr_g = F(17); pr_b = F(18); pr_m = F(19); pr_v = F(20);
    }
    #undef F

    cudaFuncSetAttribute(k_attn, cudaFuncAttributeMaxDynamicSharedMemorySize,
                         ATT_SMEM_BYTES);

    k_qkv<<<dim3(64, 6), 256>>>(x, w_qk, w_v,
                                qk_g, qk_b, qk_m, qk_v,
                                v_g, v_b, v_m, v_v);
    k_pe<<<(B_ * C_ * NPIX) / 256, 256>>>(w_pe, pe_g, pe_b, pe_m, pe_v);
    k_attn<<<dim3(8, 64), 256, ATT_SMEM_BYTES>>>();
    k_proj<<<dim3(64, 2), 256>>>(w_proj, pr_g, pr_b, pr_m, pr_v, (float*)d_out);
}